// round 1
// baseline (speedup 1.0000x reference)
#include <cuda_runtime.h>
#include <math.h>

// Problem dims (fixed by the reference)
#define BB 4
#define SS 2048
#define DD 1024
#define MS (BB*SS)          // 8192 total rows
#define OUT_ELEMS (MS*DD)   // 8388608 attention outputs, scalar at index OUT_ELEMS

// Static scratch (allocation-free rule): q,k,v (32MB each), probs (64MB), entropy rows
__device__ float g_q[MS*DD];
__device__ float g_k[MS*DD];
__device__ float g_v[MS*DD];
__device__ float g_p[(size_t)BB*SS*SS];
__device__ float g_ent[MS];

// ---------------------------------------------------------------------------
// 128x128x16 tiled SGEMM, 256 threads, 8x8 per-thread microkernel.
// TRANS_B=false: C[M,N] = A[M,K](row) * B[K,N](row)  (+ optional bias[col])
// TRANS_B=true : C[M,N] = A[M,K](row) * B[N,K](row)^T
// Batched via blockIdx.z with element strides sA/sB/sC.
// All dims are multiples of tile sizes for this problem -> no bounds checks.
// ---------------------------------------------------------------------------
template<bool TRANS_B>
__global__ __launch_bounds__(256, 2)
void gemm128(const float* __restrict__ A, const float* __restrict__ B,
             const float* __restrict__ bias, float* __restrict__ C,
             int M, int N, int K, long sA, long sB, long sC)
{
    __shared__ float As[16][132];   // padded to kill scatter-store conflicts
    __shared__ float Bs[16][132];

    const int bz = blockIdx.z;
    A += (long)bz * sA;
    B += (long)bz * sB;
    C += (long)bz * sC;

    const int bx = blockIdx.x;      // N tile
    const int by = blockIdx.y;      // M tile
    const int tid = threadIdx.x;
    const int tx = tid & 15;        // 16 col-groups of 8
    const int ty = tid >> 4;        // 16 row-groups of 8

    float acc[8][8];
    #pragma unroll
    for (int i = 0; i < 8; i++)
        #pragma unroll
        for (int j = 0; j < 8; j++) acc[i][j] = 0.f;

    for (int k0 = 0; k0 < K; k0 += 16) {
        // A tile: 128 rows x 16 k, transpose-scatter into As[k][row]
        #pragma unroll
        for (int p = 0; p < 2; p++) {
            int idx = tid + p * 256;
            int r = idx >> 2, c4 = (idx & 3) << 2;
            float4 va = *(const float4*)(A + (long)(by * 128 + r) * K + k0 + c4);
            As[c4 + 0][r] = va.x; As[c4 + 1][r] = va.y;
            As[c4 + 2][r] = va.z; As[c4 + 3][r] = va.w;
        }
        if (TRANS_B) {
            // B is NxK row-major: load 128 n-rows x 16 k, transpose-scatter
            #pragma unroll
            for (int p = 0; p < 2; p++) {
                int idx = tid + p * 256;
                int r = idx >> 2, c4 = (idx & 3) << 2;
                float4 vb = *(const float4*)(B + (long)(bx * 128 + r) * K + k0 + c4);
                Bs[c4 + 0][r] = vb.x; Bs[c4 + 1][r] = vb.y;
                Bs[c4 + 2][r] = vb.z; Bs[c4 + 3][r] = vb.w;
            }
        } else {
            // B is KxN row-major: 16 k-rows x 128 cols, coalesced float4
            #pragma unroll
            for (int p = 0; p < 2; p++) {
                int idx = tid + p * 256;
                int r = idx >> 5, c4 = (idx & 31) << 2;
                float4 vb = *(const float4*)(B + (long)(k0 + r) * N + bx * 128 + c4);
                *(float4*)(&Bs[r][c4]) = vb;
            }
        }
        __syncthreads();

        #pragma unroll
        for (int kk = 0; kk < 16; kk++) {
            float a[8], b[8];
            #pragma unroll
            for (int i = 0; i < 8; i++) a[i] = As[kk][ty * 8 + i];
            #pragma unroll
            for (int j = 0; j < 8; j++) b[j] = Bs[kk][tx * 8 + j];
            #pragma unroll
            for (int i = 0; i < 8; i++)
                #pragma unroll
                for (int j = 0; j < 8; j++)
                    acc[i][j] = fmaf(a[i], b[j], acc[i][j]);
        }
        __syncthreads();
    }

    #pragma unroll
    for (int i = 0; i < 8; i++) {
        long r = by * 128 + ty * 8 + i;
        #pragma unroll
        for (int j = 0; j < 8; j += 4) {
            int c = bx * 128 + tx * 8 + j;
            float4 v;
            v.x = acc[i][j + 0]; v.y = acc[i][j + 1];
            v.z = acc[i][j + 2]; v.w = acc[i][j + 3];
            if (bias) {
                v.x += bias[c]; v.y += bias[c + 1];
                v.z += bias[c + 2]; v.w += bias[c + 3];
            }
            *(float4*)(C + r * N + c) = v;
        }
    }
}

// ---------------------------------------------------------------------------
// Row softmax + entropy. One block (256 thr) per row of 2048 scores.
// Scores arrive UNscaled; scale = 1/(sqrt(64)*temperature) applied here.
// entropy = logZ - E[s] = m + log(l) - t/l  with l=sum e^{s-m}, t=sum e^{s-m}*s
// ---------------------------------------------------------------------------
__global__ void softmax_ent(float* __restrict__ P, float* __restrict__ ent,
                            const float* __restrict__ temp)
{
    __shared__ float red[256];
    float* p = P + (long)blockIdx.x * SS;
    const int tid = threadIdx.x;
    const float scale = 1.0f / (8.0f * temp[0]);

    float v[8];
    #pragma unroll
    for (int j = 0; j < 8; j++) v[j] = p[tid + j * 256] * scale;

    float m = v[0];
    #pragma unroll
    for (int j = 1; j < 8; j++) m = fmaxf(m, v[j]);
    red[tid] = m; __syncthreads();
    #pragma unroll
    for (int s = 128; s > 0; s >>= 1) {
        if (tid < s) red[tid] = fmaxf(red[tid], red[tid + s]);
        __syncthreads();
    }
    m = red[0]; __syncthreads();

    float e[8], l = 0.f, t = 0.f;
    #pragma unroll
    for (int j = 0; j < 8; j++) {
        e[j] = __expf(v[j] - m);
        l += e[j];
        t += e[j] * v[j];
    }
    red[tid] = l; __syncthreads();
    #pragma unroll
    for (int s = 128; s > 0; s >>= 1) {
        if (tid < s) red[tid] += red[tid + s];
        __syncthreads();
    }
    l = red[0]; __syncthreads();
    red[tid] = t; __syncthreads();
    #pragma unroll
    for (int s = 128; s > 0; s >>= 1) {
        if (tid < s) red[tid] += red[tid + s];
        __syncthreads();
    }
    t = red[0]; __syncthreads();

    const float inv = 1.0f / l;
    #pragma unroll
    for (int j = 0; j < 8; j++) p[tid + j * 256] = e[j] * inv;

    if (tid == 0) ent[blockIdx.x] = m + logf(l) - t * inv;
}

// Deterministic mean of the 8192 per-row entropies -> out scalar
__global__ void ent_reduce(const float* __restrict__ ent, float* __restrict__ out)
{
    __shared__ float red[256];
    const int tid = threadIdx.x;
    float s = 0.f;
    for (int i = tid; i < MS; i += 256) s += ent[i];
    red[tid] = s; __syncthreads();
    #pragma unroll
    for (int k = 128; k > 0; k >>= 1) {
        if (tid < k) red[tid] += red[tid + k];
        __syncthreads();
    }
    if (tid == 0) out[0] = red[0] / (float)MS;
}

extern "C" void kernel_launch(void* const* d_in, const int* in_sizes, int n_in,
                              void* d_out, int out_size)
{
    const float* x    = (const float*)d_in[0];
    const float* Wq   = (const float*)d_in[1];
    const float* bq   = (const float*)d_in[2];
    const float* Wk   = (const float*)d_in[3];
    const float* bk   = (const float*)d_in[4];
    const float* Wv   = (const float*)d_in[5];
    const float* bv   = (const float*)d_in[6];
    const float* temp = (const float*)d_in[7];
    float* out = (float*)d_out;

    float *q, *k, *v, *p, *ent;
    cudaGetSymbolAddress((void**)&q,   g_q);
    cudaGetSymbolAddress((void**)&k,   g_k);
    cudaGetSymbolAddress((void**)&v,   g_v);
    cudaGetSymbolAddress((void**)&p,   g_p);
    cudaGetSymbolAddress((void**)&ent, g_ent);

    // 1) Projections: (8192x1024) = x (8192x1024) @ W (1024x1024) + b
    {
        dim3 grid(DD / 128, MS / 128, 1);
        gemm128<false><<<grid, 256>>>(x, Wq, bq, q, MS, DD, DD, 0, 0, 0);
        gemm128<false><<<grid, 256>>>(x, Wk, bk, k, MS, DD, DD, 0, 0, 0);
        gemm128<false><<<grid, 256>>>(x, Wv, bv, v, MS, DD, DD, 0, 0, 0);
    }
    // 2) Scores (unscaled): per batch, S = q @ k^T  (2048x2048, K=1024)
    {
        dim3 grid(SS / 128, SS / 128, BB);
        gemm128<true><<<grid, 256>>>(q, k, nullptr, p, SS, SS, DD,
                                     (long)SS * DD, (long)SS * DD, (long)SS * SS);
    }
    // 3) Softmax + entropy per row (scale applied here, reads temperature)
    softmax_ent<<<MS, 256>>>(p, ent, temp);

    // 4) Output: per batch, O = probs @ v  (2048x1024, K=2048)
    {
        dim3 grid(DD / 128, SS / 128, BB);
        gemm128<false><<<grid, 256>>>(p, v, nullptr, out, SS, DD, SS,
                                      (long)SS * SS, (long)SS * DD, (long)SS * DD);
    }
    // 5) Entropy mean scalar
    ent_reduce<<<1, 256>>>(ent, out + OUT_ELEMS);
}

// round 3
// speedup vs baseline: 3.5830x; 3.5830x over previous
#include <cuda_runtime.h>
#include <cuda_bf16.h>
#include <math.h>
#include <stdint.h>

// Problem dims (fixed)
#define BB 4
#define SS 2048
#define DD 1024
#define MS (BB*SS)          // 8192 rows total
#define OUT_ELEMS (MS*DD)

// smem tile geometry: rows are 32 bf16 (64B) padded to 80B (conflict-free)
#define ROWB   80
#define TILEB  (128*ROWB)   // 10240 B per operand tile
#define STAGEB (4*TILEB)    // Ah, Al, Bh, Bl
#define SMEMB  (2*STAGEB)   // double buffered = 81920 B

// ---------------------------------------------------------------------------
// PTX helpers (sm_80-level only: cp.async, ldmatrix, mma.sync bf16)
// ---------------------------------------------------------------------------
__device__ __forceinline__ uint32_t smem_u32(const void* p) {
    uint32_t a;
    asm("{ .reg .u64 t; cvta.to.shared.u64 t, %1; cvt.u32.u64 %0, t; }" : "=r"(a) : "l"(p));
    return a;
}
#define CP16(d, s) asm volatile("cp.async.cg.shared.global [%0], [%1], 16;" :: "r"(d), "l"(s))
#define CPCOMMIT() asm volatile("cp.async.commit_group;" ::: "memory")
#define CPWAIT(n)  asm volatile("cp.async.wait_group %0;" :: "n"(n) : "memory")

__device__ __forceinline__ void ldsm4(uint32_t* r, uint32_t a) {
    asm volatile("ldmatrix.sync.aligned.m8n8.x4.shared.b16 {%0,%1,%2,%3}, [%4];"
                 : "=r"(r[0]), "=r"(r[1]), "=r"(r[2]), "=r"(r[3]) : "r"(a));
}
__device__ __forceinline__ void mma16816(float* c, const uint32_t* a, const uint32_t* b) {
    asm volatile("mma.sync.aligned.m16n8k16.row.col.f32.bf16.bf16.f32 "
                 "{%0,%1,%2,%3}, {%4,%5,%6,%7}, {%8,%9}, {%0,%1,%2,%3};"
                 : "+f"(c[0]), "+f"(c[1]), "+f"(c[2]), "+f"(c[3])
                 : "r"(a[0]), "r"(a[1]), "r"(a[2]), "r"(a[3]), "r"(b[0]), "r"(b[1]));
}

// ---------------------------------------------------------------------------
// Static scratch (allocation-free rule)
// ---------------------------------------------------------------------------
__device__ __align__(256) __nv_bfloat16 g_xh[MS*DD], g_xl[MS*DD];
__device__ __align__(256) __nv_bfloat16 g_wth[3*DD*DD], g_wtl[3*DD*DD];
__device__ __align__(256) __nv_bfloat16 g_qh[MS*DD], g_ql[MS*DD];
__device__ __align__(256) __nv_bfloat16 g_kh[MS*DD], g_kl[MS*DD];
__device__ __align__(256) float          g_v[MS*DD];
__device__ __align__(256) __nv_bfloat16 g_vth[(size_t)BB*DD*SS], g_vtl[(size_t)BB*DD*SS];
__device__ __align__(256) float          g_p[(size_t)BB*SS*SS];
__device__ __align__(256) __nv_bfloat16 g_ph[(size_t)BB*SS*SS], g_pl[(size_t)BB*SS*SS];
__device__ __align__(256) float          g_ent[MS];

// ---------------------------------------------------------------------------
// bf16 split GEMM via mma.sync:
//   C[M,N] = (Ah+Al)[M,K] x (Bh+Bl)[N,K]^T   (3 MMAs: hh + hl + lh)
// CTA tile 128x128, K-chunk 32, 256 threads = 8 warps (4 in M x 2 in N),
// warp tile 32x64 (mfrags=2 x m16, nfrags=8 x n8), cp.async double buffer.
// EPI 0: fp32 store (+optional bias). EPI 1: bf16 hi/lo split store (+bias).
// ---------------------------------------------------------------------------
template<int EPI>
__global__ __launch_bounds__(256)
void mma_gemm(const __nv_bfloat16* __restrict__ Ah, const __nv_bfloat16* __restrict__ Al,
              const __nv_bfloat16* __restrict__ Bh, const __nv_bfloat16* __restrict__ Bl,
              const float* __restrict__ bias, float* __restrict__ Cf,
              __nv_bfloat16* __restrict__ Oh, __nv_bfloat16* __restrict__ Ol,
              int N, int K, long sA, long sB, long sC)
{
    extern __shared__ char sm[];
    const uint32_t sb = smem_u32(sm);
    const int tid = threadIdx.x, lane = tid & 31, warp = tid >> 5;
    const int wm = warp & 3, wn = warp >> 2;     // 4 M-warps x 2 N-warps
    const int bz = blockIdx.z;

    const __nv_bfloat16* src[4] = {
        Ah + (long)bz * sA + (long)blockIdx.y * 128 * K,
        Al + (long)bz * sA + (long)blockIdx.y * 128 * K,
        Bh + (long)bz * sB + (long)blockIdx.x * 128 * K,
        Bl + (long)bz * sB + (long)blockIdx.x * 128 * K };

    float acc[2][8][4];
    #pragma unroll
    for (int a = 0; a < 2; a++)
        #pragma unroll
        for (int b = 0; b < 8; b++)
            #pragma unroll
            for (int c = 0; c < 4; c++) acc[a][b][c] = 0.f;

    const int NC = K >> 5;

    // ---- g2s loader: 4 tiles x 128 rows x 64B, 16B per cp.async ----
    auto load_stage = [&](int c) {
        const uint32_t dstS = sb + (uint32_t)(c & 1) * STAGEB;
        const long kof = (long)c * 32;
        #pragma unroll
        for (int t = 0; t < 4; t++) {
            #pragma unroll
            for (int p = 0; p < 2; p++) {
                const int u = tid + p * 256;
                const int r = u >> 2, s2 = u & 3;
                CP16(dstS + t * TILEB + r * ROWB + s2 * 16,
                     src[t] + (long)r * K + kof + s2 * 8);
            }
        }
        CPCOMMIT();
    };

    load_stage(0);
    if (NC > 1) load_stage(1);

    for (int c = 0; c < NC; c++) {
        if (c + 1 < NC) { CPWAIT(1); } else { CPWAIT(0); }
        __syncthreads();

        const uint32_t stb = sb + (uint32_t)(c & 1) * STAGEB;
        #pragma unroll
        for (int ks = 0; ks < 2; ks++) {
            uint32_t aHi[2][4], aLo[2][4], bHi[8][2], bLo[8][2];
            // A fragments: lanes 0-15 -> rows, lanes 16-31 -> +16B col
            {
                const int rA   = wm * 32 + (lane & 15);
                const int colA = ks * 32 + ((lane >> 4) << 4);
                #pragma unroll
                for (int mf = 0; mf < 2; mf++) {
                    const uint32_t ad = stb + (rA + mf * 16) * ROWB + colA;
                    ldsm4(aHi[mf], ad);
                    ldsm4(aLo[mf], ad + TILEB);
                }
            }
            // B fragments: x4 covers two n8 frags (rows n..n+15) x k16
            {
                const int rB   = wn * 64 + ((lane >> 4) & 1) * 8 + (lane & 7);
                const int colB = ks * 32 + ((lane >> 3) & 1) * 16;
                #pragma unroll
                for (int g = 0; g < 4; g++) {
                    const uint32_t bd = stb + 2 * TILEB + (rB + g * 16) * ROWB + colB;
                    uint32_t t4[4];
                    ldsm4(t4, bd);
                    bHi[2*g][0] = t4[0]; bHi[2*g][1] = t4[1];
                    bHi[2*g+1][0] = t4[2]; bHi[2*g+1][1] = t4[3];
                    ldsm4(t4, bd + TILEB);
                    bLo[2*g][0] = t4[0]; bLo[2*g][1] = t4[1];
                    bLo[2*g+1][0] = t4[2]; bLo[2*g+1][1] = t4[3];
                }
            }
            #pragma unroll
            for (int mf = 0; mf < 2; mf++)
                #pragma unroll
                for (int nf = 0; nf < 8; nf++) {
                    mma16816(acc[mf][nf], aHi[mf], bHi[nf]);
                    mma16816(acc[mf][nf], aHi[mf], bLo[nf]);
                    mma16816(acc[mf][nf], aLo[mf], bHi[nf]);
                }
        }
        __syncthreads();
        if (c + 2 < NC) load_stage(c + 2);
    }

    // ---- epilogue: regs -> gmem ----
    const long rbase = (long)blockIdx.y * 128 + wm * 32 + (lane >> 2);
    const int  cbase = blockIdx.x * 128 + wn * 64 + 2 * (lane & 3);
    #pragma unroll
    for (int mf = 0; mf < 2; mf++)
        #pragma unroll
        for (int rh = 0; rh < 2; rh++) {
            const long r = rbase + mf * 16 + rh * 8;
            #pragma unroll
            for (int nf = 0; nf < 8; nf++) {
                float v0 = acc[mf][nf][rh * 2 + 0];
                float v1 = acc[mf][nf][rh * 2 + 1];
                const int col = cbase + nf * 8;
                if (bias) { v0 += bias[col]; v1 += bias[col + 1]; }
                if (EPI == 0) {
                    float2 f2; f2.x = v0; f2.y = v1;
                    *(float2*)(Cf + (long)bz * sC + r * N + col) = f2;
                } else {
                    __nv_bfloat16 h0 = __float2bfloat16(v0);
                    __nv_bfloat16 h1 = __float2bfloat16(v1);
                    __nv_bfloat162 hh; hh.x = h0; hh.y = h1;
                    __nv_bfloat162 ll;
                    ll.x = __float2bfloat16(v0 - __bfloat162float(h0));
                    ll.y = __float2bfloat16(v1 - __bfloat162float(h1));
                    *(__nv_bfloat162*)(Oh + (long)bz * sC + r * N + col) = hh;
                    *(__nv_bfloat162*)(Ol + (long)bz * sC + r * N + col) = ll;
                }
            }
        }
}

// ---------------------------------------------------------------------------
// fp32 -> bf16 hi/lo elementwise split
// ---------------------------------------------------------------------------
__global__ void split_kernel(const float* __restrict__ in, __nv_bfloat16* __restrict__ oh,
                             __nv_bfloat16* __restrict__ ol, int n)
{
    int i = blockIdx.x * 256 + threadIdx.x;
    if (i < n) {
        float v = in[i];
        __nv_bfloat16 h = __float2bfloat16(v);
        oh[i] = h;
        ol[i] = __float2bfloat16(v - __bfloat162float(h));
    }
}

// ---------------------------------------------------------------------------
// Batched transpose + split: in [R,C] fp32 -> out [C,R] bf16 hi/lo
// ---------------------------------------------------------------------------
__global__ void transpose_split(const float* __restrict__ in, __nv_bfloat16* __restrict__ oh,
                                __nv_bfloat16* __restrict__ ol, int R, int C, long sIn, long sOut)
{
    __shared__ float t[32][33];
    in += (long)blockIdx.z * sIn;
    oh += (long)blockIdx.z * sOut;
    ol += (long)blockIdx.z * sOut;
    const int c0 = blockIdx.x * 32, rr0 = blockIdx.y * 32;
    const int tx = threadIdx.x, ty = threadIdx.y;
    #pragma unroll
    for (int k = 0; k < 32; k += 8)
        t[ty + k][tx] = in[(long)(rr0 + ty + k) * C + c0 + tx];
    __syncthreads();
    #pragma unroll
    for (int k = 0; k < 32; k += 8) {
        float v = t[tx][ty + k];
        __nv_bfloat16 h = __float2bfloat16(v);
        long o = (long)(c0 + ty + k) * R + rr0 + tx;
        oh[o] = h;
        ol[o] = __float2bfloat16(v - __bfloat162float(h));
    }
}

// ---------------------------------------------------------------------------
// Row softmax + entropy; writes probs as bf16 hi/lo (PV GEMM A operand)
// ---------------------------------------------------------------------------
__global__ void softmax_ent(const float* __restrict__ P, __nv_bfloat16* __restrict__ Ph,
                            __nv_bfloat16* __restrict__ Pl, float* __restrict__ ent,
                            const float* __restrict__ temp)
{
    __shared__ float red[256];
    const float* p = P + (long)blockIdx.x * SS;
    __nv_bfloat16* oh = Ph + (long)blockIdx.x * SS;
    __nv_bfloat16* ol = Pl + (long)blockIdx.x * SS;
    const int tid = threadIdx.x;
    const float scale = 1.0f / (8.0f * temp[0]);

    float v[8];
    #pragma unroll
    for (int j = 0; j < 8; j++) v[j] = p[tid + j * 256] * scale;

    float m = v[0];
    #pragma unroll
    for (int j = 1; j < 8; j++) m = fmaxf(m, v[j]);
    red[tid] = m; __syncthreads();
    #pragma unroll
    for (int s = 128; s > 0; s >>= 1) {
        if (tid < s) red[tid] = fmaxf(red[tid], red[tid + s]);
        __syncthreads();
    }
    m = red[0]; __syncthreads();

    float e[8], l = 0.f, t = 0.f;
    #pragma unroll
    for (int j = 0; j < 8; j++) {
        e[j] = __expf(v[j] - m);
        l += e[j];
        t += e[j] * v[j];
    }
    red[tid] = l; __syncthreads();
    #pragma unroll
    for (int s = 128; s > 0; s >>= 1) {
        if (tid < s) red[tid] += red[tid + s];
        __syncthreads();
    }
    l = red[0]; __syncthreads();
    red[tid] = t; __syncthreads();
    #pragma unroll
    for (int s = 128; s > 0; s >>= 1) {
        if (tid < s) red[tid] += red[tid + s];
        __syncthreads();
    }
    t = red[0]; __syncthreads();

    const float inv = 1.0f / l;
    #pragma unroll
    for (int j = 0; j < 8; j++) {
        float pr = e[j] * inv;
        __nv_bfloat16 h = __float2bfloat16(pr);
        oh[tid + j * 256] = h;
        ol[tid + j * 256] = __float2bfloat16(pr - __bfloat162float(h));
    }
    if (tid == 0) ent[blockIdx.x] = m + logf(l) - t * inv;
}

__global__ void ent_reduce(const float* __restrict__ ent, float* __restrict__ out)
{
    __shared__ float red[256];
    const int tid = threadIdx.x;
    float s = 0.f;
    for (int i = tid; i < MS; i += 256) s += ent[i];
    red[tid] = s; __syncthreads();
    #pragma unroll
    for (int k = 128; k > 0; k >>= 1) {
        if (tid < k) red[tid] += red[tid + k];
        __syncthreads();
    }
    if (tid == 0) out[0] = red[0] / (float)MS;
}

// ---------------------------------------------------------------------------
extern "C" void kernel_launch(void* const* d_in, const int* in_sizes, int n_in,
                              void* d_out, int out_size)
{
    const float* x    = (const float*)d_in[0];
    const float* Wq   = (const float*)d_in[1];
    const float* bq   = (const float*)d_in[2];
    const float* Wk   = (const float*)d_in[3];
    const float* bk   = (const float*)d_in[4];
    const float* Wv   = (const float*)d_in[5];
    const float* bv   = (const float*)d_in[6];
    const float* temp = (const float*)d_in[7];
    float* out = (float*)d_out;

    __nv_bfloat16 *xh, *xl, *wth, *wtl, *qh, *ql, *kh, *kl, *vth, *vtl, *pph, *ppl;
    float *v, *p, *ent;
    cudaGetSymbolAddress((void**)&xh,  g_xh);  cudaGetSymbolAddress((void**)&xl,  g_xl);
    cudaGetSymbolAddress((void**)&wth, g_wth); cudaGetSymbolAddress((void**)&wtl, g_wtl);
    cudaGetSymbolAddress((void**)&qh,  g_qh);  cudaGetSymbolAddress((void**)&ql,  g_ql);
    cudaGetSymbolAddress((void**)&kh,  g_kh);  cudaGetSymbolAddress((void**)&kl,  g_kl);
    cudaGetSymbolAddress((void**)&v,   g_v);
    cudaGetSymbolAddress((void**)&vth, g_vth); cudaGetSymbolAddress((void**)&vtl, g_vtl);
    cudaGetSymbolAddress((void**)&p,   g_p);
    cudaGetSymbolAddress((void**)&pph, g_ph);  cudaGetSymbolAddress((void**)&ppl, g_pl);
    cudaGetSymbolAddress((void**)&ent, g_ent);

    cudaFuncSetAttribute(mma_gemm<0>, cudaFuncAttributeMaxDynamicSharedMemorySize, SMEMB);
    cudaFuncSetAttribute(mma_gemm<1>, cudaFuncAttributeMaxDynamicSharedMemorySize, SMEMB);

    // 1) Split x; transpose+split weights (W[K,N] -> W^T[N,K] hi/lo)
    split_kernel<<<(MS*DD + 255) / 256, 256>>>(x, xh, xl, MS*DD);
    {
        dim3 blk(32, 8);
        dim3 grd(DD / 32, DD / 32, 1);
        transpose_split<<<grd, blk>>>(Wq, wth + 0*DD*DD, wtl + 0*DD*DD, DD, DD, 0, 0);
        transpose_split<<<grd, blk>>>(Wk, wth + 1*DD*DD, wtl + 1*DD*DD, DD, DD, 0, 0);
        transpose_split<<<grd, blk>>>(Wv, wth + 2*DD*DD, wtl + 2*DD*DD, DD, DD, 0, 0);
    }
    // 2) Projections (M=8192, N=1024, K=1024)
    {
        dim3 grd(DD / 128, MS / 128, 1);
        mma_gemm<1><<<grd, 256, SMEMB>>>(xh, xl, wth + 0*DD*DD, wtl + 0*DD*DD,
                                         bq, nullptr, qh, ql, DD, DD, 0, 0, 0);
        mma_gemm<1><<<grd, 256, SMEMB>>>(xh, xl, wth + 1*DD*DD, wtl + 1*DD*DD,
                                         bk, nullptr, kh, kl, DD, DD, 0, 0, 0);
        mma_gemm<0><<<grd, 256, SMEMB>>>(xh, xl, wth + 2*DD*DD, wtl + 2*DD*DD,
                                         bv, v, nullptr, nullptr, DD, DD, 0, 0, 0);
    }
    // 3) v -> v^T hi/lo per batch ([S,D] -> [D,S])
    {
        dim3 blk(32, 8);
        dim3 grd(DD / 32, SS / 32, BB);
        transpose_split<<<grd, blk>>>(v, vth, vtl, SS, DD, (long)SS * DD, (long)DD * SS);
    }
    // 4) Scores (per batch: 2048x2048, K=1024), unscaled fp32
    {
        dim3 grd(SS / 128, SS / 128, BB);
        mma_gemm<0><<<grd, 256, SMEMB>>>(qh, ql, kh, kl, nullptr, p, nullptr, nullptr,
                                         SS, DD, (long)SS*DD, (long)SS*DD, (long)SS*SS);
    }
    // 5) Softmax + entropy; probs -> bf16 hi/lo
    softmax_ent<<<MS, 256>>>(p, pph, ppl, ent, temp);
    // 6) PV (per batch: 2048x1024, K=2048) -> out fp32
    {
        dim3 grd(DD / 128, SS / 128, BB);
        mma_gemm<0><<<grd, 256, SMEMB>>>(pph, ppl, vth, vtl, nullptr, out, nullptr, nullptr,
                                         DD, SS, (long)SS*SS, (long)DD*SS, (long)SS*DD);
    }
    // 7) Entropy mean scalar
    ent_reduce<<<1, 256>>>(ent, out + OUT_ELEMS);
}

// round 4
// speedup vs baseline: 4.3012x; 1.2004x over previous
#include <cuda_runtime.h>
#include <cuda_bf16.h>
#include <math.h>
#include <stdint.h>

// Problem dims (fixed)
#define BB 4
#define SS 2048
#define DD 1024
#define MS (BB*SS)          // 8192 rows total
#define OUT_ELEMS (MS*DD)

// smem tile geometry: rows are 32 bf16 (64B) padded to 80B (conflict-free)
#define ROWB   80
#define TILEB  (128*ROWB)   // 10240 B per operand tile
#define STAGEB (4*TILEB)    // Ah, Al, Bh, Bl
#define SMEMB  (2*STAGEB)   // double buffered = 81920 B

// ---------------------------------------------------------------------------
// PTX helpers (sm_80-level only: cp.async, ldmatrix, mma.sync bf16)
// ---------------------------------------------------------------------------
__device__ __forceinline__ uint32_t smem_u32(const void* p) {
    uint32_t a;
    asm("{ .reg .u64 t; cvta.to.shared.u64 t, %1; cvt.u32.u64 %0, t; }" : "=r"(a) : "l"(p));
    return a;
}
#define CP16(d, s) asm volatile("cp.async.cg.shared.global [%0], [%1], 16;" :: "r"(d), "l"(s))
#define CPCOMMIT() asm volatile("cp.async.commit_group;" ::: "memory")
#define CPWAIT(n)  asm volatile("cp.async.wait_group %0;" :: "n"(n) : "memory")

__device__ __forceinline__ void ldsm4(uint32_t* r, uint32_t a) {
    asm volatile("ldmatrix.sync.aligned.m8n8.x4.shared.b16 {%0,%1,%2,%3}, [%4];"
                 : "=r"(r[0]), "=r"(r[1]), "=r"(r[2]), "=r"(r[3]) : "r"(a));
}
__device__ __forceinline__ void mma16816(float* c, const uint32_t* a, const uint32_t* b) {
    asm volatile("mma.sync.aligned.m16n8k16.row.col.f32.bf16.bf16.f32 "
                 "{%0,%1,%2,%3}, {%4,%5,%6,%7}, {%8,%9}, {%0,%1,%2,%3};"
                 : "+f"(c[0]), "+f"(c[1]), "+f"(c[2]), "+f"(c[3])
                 : "r"(a[0]), "r"(a[1]), "r"(a[2]), "r"(a[3]), "r"(b[0]), "r"(b[1]));
}

// ---------------------------------------------------------------------------
// Static scratch (allocation-free rule)
// ---------------------------------------------------------------------------
__device__ __align__(256) __nv_bfloat16 g_xh[MS*DD], g_xl[MS*DD];
__device__ __align__(256) __nv_bfloat16 g_wth[3*DD*DD], g_wtl[3*DD*DD];   // W^T concat [3N,K]
__device__ __align__(256) __nv_bfloat16 g_qh[MS*DD], g_ql[MS*DD];
__device__ __align__(256) __nv_bfloat16 g_kh[MS*DD], g_kl[MS*DD];
__device__ __align__(256) __nv_bfloat16 g_vh[MS*DD], g_vl[MS*DD];
__device__ __align__(256) __nv_bfloat16 g_vth[(size_t)BB*DD*SS], g_vtl[(size_t)BB*DD*SS];
__device__ __align__(256) float          g_p[(size_t)BB*SS*SS];
__device__ __align__(256) __nv_bfloat16 g_ph[(size_t)BB*SS*SS], g_pl[(size_t)BB*SS*SS];
__device__ __align__(256) float          g_ent[MS];

// Epilogue routing for the fused QKV projection (3 outputs, select by column)
struct ProjOut {
    const float* bias[3];
    __nv_bfloat16* oh[3];
    __nv_bfloat16* ol[3];
};

// ---------------------------------------------------------------------------
// bf16 split GEMM via mma.sync:
//   C[M,N] = (Ah+Al)[M,K] x (Bh+Bl)[N,K]^T   (3 MMAs: hh + hl + lh)
// CTA tile 128x128, K-chunk 32, 256 threads = 8 warps (4 M x 2 N),
// warp tile 32x64, cp.async double buffer, 2 CTAs/SM.
// EPI 0: fp32 store. EPI 1: bf16 hi/lo split store routed via ProjOut.
// ---------------------------------------------------------------------------
template<int EPI>
__global__ __launch_bounds__(256, 2)
void mma_gemm(const __nv_bfloat16* __restrict__ Ah, const __nv_bfloat16* __restrict__ Al,
              const __nv_bfloat16* __restrict__ Bh, const __nv_bfloat16* __restrict__ Bl,
              float* __restrict__ Cf, ProjOut po,
              int N, int K, long sA, long sB, long sC)
{
    extern __shared__ char sm[];
    const uint32_t sb = smem_u32(sm);
    const int tid = threadIdx.x, lane = tid & 31, warp = tid >> 5;
    const int wm = warp & 3, wn = warp >> 2;     // 4 M-warps x 2 N-warps
    const int bz = blockIdx.z;

    const __nv_bfloat16* src[4] = {
        Ah + (long)bz * sA + (long)blockIdx.y * 128 * K,
        Al + (long)bz * sA + (long)blockIdx.y * 128 * K,
        Bh + (long)bz * sB + (long)blockIdx.x * 128 * K,
        Bl + (long)bz * sB + (long)blockIdx.x * 128 * K };

    float acc[2][8][4];
    #pragma unroll
    for (int a = 0; a < 2; a++)
        #pragma unroll
        for (int b = 0; b < 8; b++)
            #pragma unroll
            for (int c = 0; c < 4; c++) acc[a][b][c] = 0.f;

    const int NC = K >> 5;

    // ---- g2s loader: 4 tiles x 128 rows x 64B, 16B per cp.async ----
    auto load_stage = [&](int c) {
        const uint32_t dstS = sb + (uint32_t)(c & 1) * STAGEB;
        const long kof = (long)c * 32;
        #pragma unroll
        for (int t = 0; t < 4; t++) {
            #pragma unroll
            for (int p = 0; p < 2; p++) {
                const int u = tid + p * 256;
                const int r = u >> 2, s2 = u & 3;
                CP16(dstS + t * TILEB + r * ROWB + s2 * 16,
                     src[t] + (long)r * K + kof + s2 * 8);
            }
        }
        CPCOMMIT();
    };

    load_stage(0);
    if (NC > 1) load_stage(1);

    for (int c = 0; c < NC; c++) {
        if (c + 1 < NC) { CPWAIT(1); } else { CPWAIT(0); }
        __syncthreads();

        const uint32_t stb = sb + (uint32_t)(c & 1) * STAGEB;
        #pragma unroll
        for (int ks = 0; ks < 2; ks++) {
            // A fragments (hi+lo): 2 m16 frags
            uint32_t aHi[2][4], aLo[2][4];
            const int rA   = wm * 32 + (lane & 15);
            const int colA = ks * 32 + ((lane >> 4) << 4);
            #pragma unroll
            for (int mf = 0; mf < 2; mf++) {
                const uint32_t ad = stb + (rA + mf * 16) * ROWB + colA;
                ldsm4(aHi[mf], ad);
                ldsm4(aLo[mf], ad + TILEB);
            }
            // B in 4 groups of 16 rows (2 n8 frags each) to cap live regs
            const int rB   = wn * 64 + ((lane >> 4) & 1) * 8 + (lane & 7);
            const int colB = ks * 32 + ((lane >> 3) & 1) * 16;
            #pragma unroll
            for (int g = 0; g < 4; g++) {
                uint32_t bh4[4], bl4[4];
                const uint32_t bd = stb + 2 * TILEB + (rB + g * 16) * ROWB + colB;
                ldsm4(bh4, bd);
                ldsm4(bl4, bd + TILEB);
                #pragma unroll
                for (int mf = 0; mf < 2; mf++) {
                    mma16816(acc[mf][2*g],   aHi[mf], bh4);
                    mma16816(acc[mf][2*g],   aHi[mf], bl4);
                    mma16816(acc[mf][2*g],   aLo[mf], bh4);
                    mma16816(acc[mf][2*g+1], aHi[mf], bh4 + 2);
                    mma16816(acc[mf][2*g+1], aHi[mf], bl4 + 2);
                    mma16816(acc[mf][2*g+1], aLo[mf], bh4 + 2);
                }
            }
        }
        __syncthreads();
        if (c + 2 < NC) load_stage(c + 2);
    }

    // ---- epilogue ----
    const long rbase = (long)blockIdx.y * 128 + wm * 32 + (lane >> 2);
    const int  gcol0 = blockIdx.x * 128;

    if (EPI == 0) {
        #pragma unroll
        for (int mf = 0; mf < 2; mf++)
            #pragma unroll
            for (int rh = 0; rh < 2; rh++) {
                const long r = rbase + mf * 16 + rh * 8;
                #pragma unroll
                for (int nf = 0; nf < 8; nf++) {
                    const int col = gcol0 + wn * 64 + 2 * (lane & 3) + nf * 8;
                    float2 f2;
                    f2.x = acc[mf][nf][rh * 2 + 0];
                    f2.y = acc[mf][nf][rh * 2 + 1];
                    *(float2*)(Cf + (long)bz * sC + r * N + col) = f2;
                }
            }
    } else {
        // whole 128-col tile lives in one of q/k/v (N blocks of 1024)
        const int which = gcol0 >> 10;
        const int lcol0 = gcol0 & 1023;
        const float* bias = po.bias[which];
        __nv_bfloat16* Oh = po.oh[which];
        __nv_bfloat16* Ol = po.ol[which];
        #pragma unroll
        for (int mf = 0; mf < 2; mf++)
            #pragma unroll
            for (int rh = 0; rh < 2; rh++) {
                const long r = rbase + mf * 16 + rh * 8;
                #pragma unroll
                for (int nf = 0; nf < 8; nf++) {
                    const int col = lcol0 + wn * 64 + 2 * (lane & 3) + nf * 8;
                    float v0 = acc[mf][nf][rh * 2 + 0] + bias[col];
                    float v1 = acc[mf][nf][rh * 2 + 1] + bias[col + 1];
                    __nv_bfloat16 h0 = __float2bfloat16(v0);
                    __nv_bfloat16 h1 = __float2bfloat16(v1);
                    __nv_bfloat162 hh; hh.x = h0; hh.y = h1;
                    __nv_bfloat162 ll;
                    ll.x = __float2bfloat16(v0 - __bfloat162float(h0));
                    ll.y = __float2bfloat16(v1 - __bfloat162float(h1));
                    *(__nv_bfloat162*)(Oh + r * DD + col) = hh;
                    *(__nv_bfloat162*)(Ol + r * DD + col) = ll;
                }
            }
    }
}

// ---------------------------------------------------------------------------
// fp32 -> bf16 hi/lo elementwise split
// ---------------------------------------------------------------------------
__global__ void split_kernel(const float* __restrict__ in, __nv_bfloat16* __restrict__ oh,
                             __nv_bfloat16* __restrict__ ol, int n)
{
    int i = blockIdx.x * 256 + threadIdx.x;
    if (i < n) {
        float v = in[i];
        __nv_bfloat16 h = __float2bfloat16(v);
        oh[i] = h;
        ol[i] = __float2bfloat16(v - __bfloat162float(h));
    }
}

// ---------------------------------------------------------------------------
// Transpose + split fp32 [R,C] -> bf16 hi/lo [C,R] (weights)
// ---------------------------------------------------------------------------
__global__ void transpose_split(const float* __restrict__ in, __nv_bfloat16* __restrict__ oh,
                                __nv_bfloat16* __restrict__ ol, int R, int C)
{
    __shared__ float t[32][33];
    const int c0 = blockIdx.x * 32, rr0 = blockIdx.y * 32;
    const int tx = threadIdx.x, ty = threadIdx.y;
    #pragma unroll
    for (int k = 0; k < 32; k += 8)
        t[ty + k][tx] = in[(long)(rr0 + ty + k) * C + c0 + tx];
    __syncthreads();
    #pragma unroll
    for (int k = 0; k < 32; k += 8) {
        float v = t[tx][ty + k];
        __nv_bfloat16 h = __float2bfloat16(v);
        long o = (long)(c0 + ty + k) * R + rr0 + tx;
        oh[o] = h;
        ol[o] = __float2bfloat16(v - __bfloat162float(h));
    }
}

// ---------------------------------------------------------------------------
// Batched bf16-pair transpose: [R,C] hi/lo -> [C,R] hi/lo (v -> v^T)
// ---------------------------------------------------------------------------
__global__ void transpose_pair(const __nv_bfloat16* __restrict__ ih, const __nv_bfloat16* __restrict__ il,
                               __nv_bfloat16* __restrict__ oh, __nv_bfloat16* __restrict__ ol,
                               int R, int C, long sIn, long sOut)
{
    __shared__ __nv_bfloat16 th[32][34], tl[32][34];
    ih += (long)blockIdx.z * sIn;  il += (long)blockIdx.z * sIn;
    oh += (long)blockIdx.z * sOut; ol += (long)blockIdx.z * sOut;
    const int c0 = blockIdx.x * 32, rr0 = blockIdx.y * 32;
    const int tx = threadIdx.x, ty = threadIdx.y;
    #pragma unroll
    for (int k = 0; k < 32; k += 8) {
        long i = (long)(rr0 + ty + k) * C + c0 + tx;
        th[ty + k][tx] = ih[i];
        tl[ty + k][tx] = il[i];
    }
    __syncthreads();
    #pragma unroll
    for (int k = 0; k < 32; k += 8) {
        long o = (long)(c0 + ty + k) * R + rr0 + tx;
        oh[o] = th[tx][ty + k];
        ol[o] = tl[tx][ty + k];
    }
}

// ---------------------------------------------------------------------------
// Row softmax + entropy; writes probs as bf16 hi/lo (PV GEMM A operand)
// ---------------------------------------------------------------------------
__global__ void softmax_ent(const float* __restrict__ P, __nv_bfloat16* __restrict__ Ph,
                            __nv_bfloat16* __restrict__ Pl, float* __restrict__ ent,
                            const float* __restrict__ temp)
{
    __shared__ float red[256];
    const float* p = P + (long)blockIdx.x * SS;
    __nv_bfloat16* oh = Ph + (long)blockIdx.x * SS;
    __nv_bfloat16* ol = Pl + (long)blockIdx.x * SS;
    const int tid = threadIdx.x;
    const float scale = 1.0f / (8.0f * temp[0]);

    float v[8];
    #pragma unroll
    for (int j = 0; j < 8; j++) v[j] = p[tid + j * 256] * scale;

    float m = v[0];
    #pragma unroll
    for (int j = 1; j < 8; j++) m = fmaxf(m, v[j]);
    red[tid] = m; __syncthreads();
    #pragma unroll
    for (int s = 128; s > 0; s >>= 1) {
        if (tid < s) red[tid] = fmaxf(red[tid], red[tid + s]);
        __syncthreads();
    }
    m = red[0]; __syncthreads();

    float e[8], l = 0.f, t = 0.f;
    #pragma unroll
    for (int j = 0; j < 8; j++) {
        e[j] = __expf(v[j] - m);
        l += e[j];
        t += e[j] * v[j];
    }
    red[tid] = l; __syncthreads();
    #pragma unroll
    for (int s = 128; s > 0; s >>= 1) {
        if (tid < s) red[tid] += red[tid + s];
        __syncthreads();
    }
    l = red[0]; __syncthreads();
    red[tid] = t; __syncthreads();
    #pragma unroll
    for (int s = 128; s > 0; s >>= 1) {
        if (tid < s) red[tid] += red[tid + s];
        __syncthreads();
    }
    t = red[0]; __syncthreads();

    const float inv = 1.0f / l;
    #pragma unroll
    for (int j = 0; j < 8; j++) {
        float pr = e[j] * inv;
        __nv_bfloat16 h = __float2bfloat16(pr);
        oh[tid + j * 256] = h;
        ol[tid + j * 256] = __float2bfloat16(pr - __bfloat162float(h));
    }
    if (tid == 0) ent[blockIdx.x] = m + logf(l) - t * inv;
}

__global__ void ent_reduce(const float* __restrict__ ent, float* __restrict__ out)
{
    __shared__ float red[256];
    const int tid = threadIdx.x;
    float s = 0.f;
    for (int i = tid; i < MS; i += 256) s += ent[i];
    red[tid] = s; __syncthreads();
    #pragma unroll
    for (int k = 128; k > 0; k >>= 1) {
        if (tid < k) red[tid] += red[tid + k];
        __syncthreads();
    }
    if (tid == 0) out[0] = red[0] / (float)MS;
}

// ---------------------------------------------------------------------------
extern "C" void kernel_launch(void* const* d_in, const int* in_sizes, int n_in,
                              void* d_out, int out_size)
{
    const float* x    = (const float*)d_in[0];
    const float* Wq   = (const float*)d_in[1];
    const float* bq   = (const float*)d_in[2];
    const float* Wk   = (const float*)d_in[3];
    const float* bk   = (const float*)d_in[4];
    const float* Wv   = (const float*)d_in[5];
    const float* bv   = (const float*)d_in[6];
    const float* temp = (const float*)d_in[7];
    float* out = (float*)d_out;

    __nv_bfloat16 *xh, *xl, *wth, *wtl, *qh, *ql, *kh, *kl, *vh, *vl, *vth, *vtl, *pph, *ppl;
    float *p, *ent;
    cudaGetSymbolAddress((void**)&xh,  g_xh);  cudaGetSymbolAddress((void**)&xl,  g_xl);
    cudaGetSymbolAddress((void**)&wth, g_wth); cudaGetSymbolAddress((void**)&wtl, g_wtl);
    cudaGetSymbolAddress((void**)&qh,  g_qh);  cudaGetSymbolAddress((void**)&ql,  g_ql);
    cudaGetSymbolAddress((void**)&kh,  g_kh);  cudaGetSymbolAddress((void**)&kl,  g_kl);
    cudaGetSymbolAddress((void**)&vh,  g_vh);  cudaGetSymbolAddress((void**)&vl,  g_vl);
    cudaGetSymbolAddress((void**)&vth, g_vth); cudaGetSymbolAddress((void**)&vtl, g_vtl);
    cudaGetSymbolAddress((void**)&p,   g_p);
    cudaGetSymbolAddress((void**)&pph, g_ph);  cudaGetSymbolAddress((void**)&ppl, g_pl);
    cudaGetSymbolAddress((void**)&ent, g_ent);

    cudaFuncSetAttribute(mma_gemm<0>, cudaFuncAttributeMaxDynamicSharedMemorySize, SMEMB);
    cudaFuncSetAttribute(mma_gemm<1>, cudaFuncAttributeMaxDynamicSharedMemorySize, SMEMB);

    ProjOut poNull = {};

    // 1) Split x; transpose+split weights into concat W^T [3*D, D]
    split_kernel<<<(MS*DD + 255) / 256, 256>>>(x, xh, xl, MS*DD);
    {
        dim3 blk(32, 8);
        dim3 grd(DD / 32, DD / 32, 1);
        transpose_split<<<grd, blk>>>(Wq, wth + 0*DD*DD, wtl + 0*DD*DD, DD, DD);
        transpose_split<<<grd, blk>>>(Wk, wth + 1*DD*DD, wtl + 1*DD*DD, DD, DD);
        transpose_split<<<grd, blk>>>(Wv, wth + 2*DD*DD, wtl + 2*DD*DD, DD, DD);
    }
    // 2) Fused QKV projection: M=8192, N=3072, K=1024 -> bf16 hi/lo outputs
    {
        ProjOut po;
        po.bias[0] = bq; po.bias[1] = bk; po.bias[2] = bv;
        po.oh[0] = qh; po.oh[1] = kh; po.oh[2] = vh;
        po.ol[0] = ql; po.ol[1] = kl; po.ol[2] = vl;
        dim3 grd(3*DD / 128, MS / 128, 1);
        mma_gemm<1><<<grd, 256, SMEMB>>>(xh, xl, wth, wtl, nullptr, po, 3*DD, DD, 0, 0, 0);
    }
    // 3) v -> v^T hi/lo per batch ([S,D] -> [D,S])
    {
        dim3 blk(32, 8);
        dim3 grd(DD / 32, SS / 32, BB);
        transpose_pair<<<grd, blk>>>(vh, vl, vth, vtl, SS, DD, (long)SS * DD, (long)DD * SS);
    }
    // 4) Scores (per batch: 2048x2048, K=1024), unscaled fp32
    {
        dim3 grd(SS / 128, SS / 128, BB);
        mma_gemm<0><<<grd, 256, SMEMB>>>(qh, ql, kh, kl, p, poNull,
                                         SS, DD, (long)SS*DD, (long)SS*DD, (long)SS*SS);
    }
    // 5) Softmax + entropy; probs -> bf16 hi/lo
    softmax_ent<<<MS, 256>>>(p, pph, ppl, ent, temp);
    // 6) PV (per batch: 2048x1024, K=2048) -> out fp32
    {
        dim3 grd(DD / 128, SS / 128, BB);
        mma_gemm<0><<<grd, 256, SMEMB>>>(pph, ppl, vth, vtl, out, poNull,
                                         DD, SS, (long)SS*SS, (long)DD*SS, (long)SS*DD);
    }
    // 7) Entropy mean scalar
    ent_reduce<<<1, 256>>>(ent, out + OUT_ELEMS);
}